// round 10
// baseline (speedup 1.0000x reference)
#include <cuda_runtime.h>
#include <cuda_fp16.h>
#include <cstdint>

// ============================================================================
// out[i,j] = w3 . relu(W2 . relu(hx_i + hy_j + b1) + b2) + b3
// B = 512, H = 512, DX = DY = 128
// ============================================================================
#define BB 512
#define HH 512

__device__ __align__(128)  float  g_hx[BB * HH];           // x@W1[:, :128]^T + b1
__device__ __align__(128)  float  g_hy[BB * HH];           // y@W1[:, 128:]^T
// W2 fp16, pre-swizzled step-major: 32 steps (nc*8 + ke) of 16KB.
// slab: row n_local (0..127) * 128B; 16B chunk c at ((c ^ (n_local&7))<<4).
__device__ __align__(1024) unsigned char g_Wsw[HH * HH * 2];

// k_main SMEM layout (dynamic, bytes)
#define OFF_A    0                         // 64 rows x 1024B (fp16, swizzled)
#define OFF_W(s) (65536 + (s) * 16384)     // 2 x 16KB W slabs
#define OFF_B2   98304                     // 512 f32
#define OFF_W3   100352                    // 512 f32
#define OFF_MB   102400                    // 2 mbarriers (16B) + 2 counters (8B)
#define SMEM_BYTES 102528

static __device__ __forceinline__ uint32_t smem_u32(const void* p) {
    uint32_t a;
    asm("{ .reg .u64 t; cvta.to.shared.u64 t, %1; cvt.u32.u64 %0, t; }" : "=r"(a) : "l"(p));
    return a;
}
#define MBAR_INIT(addr, cnt) \
    asm volatile("mbarrier.init.shared.b64 [%0], %1;" :: "r"(addr), "r"(cnt) : "memory")
#define MBAR_EXPECT_TX(addr, bytes) \
    asm volatile("mbarrier.arrive.expect_tx.shared.b64 _, [%0], %1;" :: "r"(addr), "r"(bytes) : "memory")
#define MBAR_WAIT(addr, ph) do {                                                \
    uint32_t _m = (addr), _p = (ph), _d;                                        \
    asm volatile("{\n\t.reg .pred p;\n\t"                                       \
        "mbarrier.try_wait.parity.acquire.cta.shared::cta.b64 p, [%1], %2;\n\t" \
        "selp.b32 %0, 1, 0, p;\n\t}" : "=r"(_d) : "r"(_m), "r"(_p) : "memory"); \
    if (!_d) {                                                                  \
        asm volatile("{\n\t.reg .pred P;\n\tWL%=:\n\t"                          \
            "mbarrier.try_wait.parity.acquire.cta.shared::cta.b64 P, [%0], %1, 0x989680;\n\t" \
            "@P bra.uni WD%=;\n\tbra.uni WL%=;\n\tWD%=:\n\t}"                   \
            :: "r"(_m), "r"(_p) : "memory");                                    \
    }                                                                           \
} while (0)
static __device__ __forceinline__ void bulk_g2s(uint32_t dst, const void* src,
                                                uint32_t bytes, uint32_t mbar) {
    asm volatile(
        "cp.async.bulk.shared::cluster.global.mbarrier::complete_tx::bytes [%0], [%1], %2, [%3];"
        :: "r"(dst), "l"(src), "r"(bytes), "r"(mbar) : "memory");
}
static __device__ __forceinline__ void ldsm_x4(uint32_t& r0, uint32_t& r1, uint32_t& r2,
                                               uint32_t& r3, uint32_t addr) {
    asm volatile("ldmatrix.sync.aligned.m8n8.x4.shared.b16 {%0,%1,%2,%3}, [%4];"
                 : "=r"(r0), "=r"(r1), "=r"(r2), "=r"(r3) : "r"(addr));
}
// fp16-accumulator MMA: D (half2 x2) += A x B
static __device__ __forceinline__ void mma16816h(uint32_t* d, const uint32_t* a,
                                                 const uint32_t* b) {
    asm volatile(
        "mma.sync.aligned.m16n8k16.row.col.f16.f16.f16.f16 "
        "{%0,%1}, {%2,%3,%4,%5}, {%6,%7}, {%0,%1};"
        : "+r"(d[0]), "+r"(d[1])
        : "r"(a[0]), "r"(a[1]), "r"(a[2]), "r"(a[3]), "r"(b[0]), "r"(b[1]));
}

// ============================================================================
// Kernel 1: prep = first linear (blocks 0..511) + W2 quant/swizzle (512..1023)
// ============================================================================
__global__ void __launch_bounds__(256) k_prep(const float* __restrict__ x,
                                              const float* __restrict__ y,
                                              const float* __restrict__ W1,
                                              const float* __restrict__ b1,
                                              const float* __restrict__ W2) {
    int b = blockIdx.x;
    if (b >= 512) {
        // quant: 2 consecutive h per thread; layout = 32 steps of 16KB
        int idx = ((b - 512) * 256 + threadIdx.x) * 2;
        int n = idx >> 9, h = idx & 511;
        int nc = n >> 7, n_local = n & 127;
        int ke = h >> 6, k_local = h & 63;
        int step = nc * 8 + ke;
        uint32_t c = (uint32_t)(k_local >> 3);
        uint32_t off = (uint32_t)n_local * 128 +
                       ((c ^ (uint32_t)(n_local & 7)) << 4) + (uint32_t)(k_local & 7) * 2;
        float2 v = *(const float2*)(W2 + (size_t)n * HH + h);
        __half2 hv;
        hv.x = __float2half_rn(v.x);
        hv.y = __float2half_rn(v.y);
        *(uint32_t*)(g_Wsw + (size_t)step * 16384 + off) = *(uint32_t*)&hv;
        return;
    }
    __shared__ float xs_t[128][33];
    __shared__ float ws[32][128];
    int path = b >> 8;
    int rem = b & 255;
    int i0 = (rem & 15) * 32, h0 = (rem >> 4) * 32;
    const float* src = path ? y : x;
    int colOff = path ? 128 : 0;

    for (int v = threadIdx.x; v < 32 * 128; v += 256) {
        int i = v >> 7, d = v & 127;
        xs_t[d][i] = src[(i0 + i) * 128 + d];
    }
    for (int v = threadIdx.x; v < 32 * 32; v += 256) {
        int r = v >> 5, c4 = v & 31;
        ((float4*)&ws[r][0])[c4] = ((const float4*)&W1[(h0 + r) * 256 + colOff])[c4];
    }
    __syncthreads();

    int ti = threadIdx.x & 31, th = threadIdx.x >> 5;
    float acc0 = 0.f, acc1 = 0.f, acc2 = 0.f, acc3 = 0.f;
    #pragma unroll 4
    for (int d = 0; d < 128; d++) {
        float xv = xs_t[d][ti];
        acc0 = fmaf(xv, ws[th * 4 + 0][d], acc0);
        acc1 = fmaf(xv, ws[th * 4 + 1][d], acc1);
        acc2 = fmaf(xv, ws[th * 4 + 2][d], acc2);
        acc3 = fmaf(xv, ws[th * 4 + 3][d], acc3);
    }
    float* dst = path ? g_hy : g_hx;
    int i = i0 + ti;
    int hb = h0 + th * 4;
    float a0 = path ? 0.f : b1[hb + 0];
    float a1 = path ? 0.f : b1[hb + 1];
    float a2 = path ? 0.f : b1[hb + 2];
    float a3 = path ? 0.f : b1[hb + 3];
    dst[i * HH + hb + 0] = acc0 + a0;
    dst[i * HH + hb + 1] = acc1 + a1;
    dst[i * HH + hb + 2] = acc2 + a2;
    dst[i * HH + hb + 3] = acc3 + a3;
}

// ============================================================================
// Kernel 2: main pair-GEMM + fused epilogue.  grid 4096, block 128 (4 warps)
//   CTA tile: 64 pairs (8i x 8j), ~100KB SMEM -> 2 CTAs/SM.
//   32 steps of 16KB W (cp.async.bulk, 2-deep, last-warp refetch).
//   Warp tile m64 x n32.  MMA uses fp16 accumulators (dh, reset every step,
//   4-MMA chains only) folded into persistent fp32 dacc each step.
// ============================================================================
__global__ void __launch_bounds__(128, 2) k_main(const float* __restrict__ b2g,
                                                 const float* __restrict__ w3g,
                                                 const float* __restrict__ b3g,
                                                 float* __restrict__ out) {
    extern __shared__ __align__(1024) unsigned char smem[];
    uint32_t sb = smem_u32(smem);
    int tid = threadIdx.x, wid = tid >> 5, lane = tid & 31;
    int t = blockIdx.x;
    int i0 = (t >> 6) * 8, j0 = (t & 63) * 8;

    float* b2s = (float*)(smem + OFF_B2);
    float* w3s = (float*)(smem + OFF_W3);
    int* wcnt = (int*)(smem + OFF_MB + 16);

    // ---- init mbarriers/counters + kick off first two W slabs ----
    if (tid == 0) {
        MBAR_INIT(sb + OFF_MB + 0, 1);
        MBAR_INIT(sb + OFF_MB + 8, 1);
        wcnt[0] = 0;
        wcnt[1] = 0;
        asm volatile("fence.proxy.async.shared::cta;" ::: "memory");
        MBAR_EXPECT_TX(sb + OFF_MB + 0, 16384u);
        bulk_g2s(sb + OFF_W(0), g_Wsw + 0 * 16384, 16384u, sb + OFF_MB + 0);
        MBAR_EXPECT_TX(sb + OFF_MB + 8, 16384u);
        bulk_g2s(sb + OFF_W(1), g_Wsw + 1 * 16384, 16384u, sb + OFF_MB + 8);
    }

    // ---- b2 / w3 to SMEM ----
    for (int v = tid; v < 512; v += 128) {
        b2s[v] = b2g[v];
        w3s[v] = w3g[v];
    }

    // ---- build A = relu(hx_i + hy_j) fp16 (register-blocked, 2 cols/thread) ----
    #pragma unroll
    for (int hf = 0; hf < 2; hf++) {
        int kk = tid + hf * 128;  // half2 column
        float2 hyv[8];
        #pragma unroll
        for (int j = 0; j < 8; j++)
            hyv[j] = ((const float2*)(g_hy + (j0 + j) * HH))[kk];
        uint32_t base = sb + OFF_A + (uint32_t)(kk & 3) * 4;
        uint32_t chunk = (uint32_t)(kk >> 2);
        #pragma unroll
        for (int ig = 0; ig < 8; ig++) {
            float2 hx2 = ((const float2*)(g_hx + (i0 + ig) * HH))[kk];
            #pragma unroll
            for (int j = 0; j < 8; j++) {
                float v0 = fmaxf(hx2.x + hyv[j].x, 0.f);
                float v1 = fmaxf(hx2.y + hyv[j].y, 0.f);
                __half2 hv;
                hv.x = __float2half_rn(v0);
                hv.y = __float2half_rn(v1);
                uint32_t p = (uint32_t)(ig * 8 + j);
                uint32_t addr = base + p * 1024 + ((chunk ^ (p & 7)) << 4);
                asm volatile("st.shared.b32 [%0], %1;"
                             :: "r"(addr), "r"(*(uint32_t*)&hv) : "memory");
            }
        }
    }
    __syncthreads();   // A ready; mbarrier/counter inits visible

    // ---- per-warp geometry: warp tile m64 x n32 (wid = n-warp index) ----
    int n0 = wid * 32;

    uint32_t x7 = (uint32_t)(lane & 7);
    uint32_t aHi = (uint32_t)(lane >> 4);
    uint32_t aRow[4];
    #pragma unroll
    for (int mi = 0; mi < 4; mi++)
        aRow[mi] = sb + OFF_A + (uint32_t)(mi * 16 + (lane & 15)) * 1024;
    uint32_t bRowOff = (uint32_t)(n0 + (lane & 7) + ((lane >> 4) << 3)) * 128;
    uint32_t bHi = (uint32_t)((lane >> 3) & 1);

    float dacc[4][4][4];              // [mi][ni][q]  persistent fp32
    float rowacc[4][2];               // [mi][row half]
    #pragma unroll
    for (int mi = 0; mi < 4; mi++) { rowacc[mi][0] = 0.f; rowacc[mi][1] = 0.f; }

    #pragma unroll 1
    for (int st = 0; st < 32; st++) {
        int s = st & 1, ke = st & 7;
        MBAR_WAIT(sb + OFF_MB + s * 8, (st >> 1) & 1);

        if (ke == 0) {
            #pragma unroll
            for (int mi = 0; mi < 4; mi++)
                #pragma unroll
                for (int ni = 0; ni < 4; ni++)
                    #pragma unroll
                    for (int q = 0; q < 4; q++) dacc[mi][ni][q] = 0.f;
        }

        // fp16 accumulators for this slab only (4-MMA chains)
        uint32_t dh[4][4][2];
        #pragma unroll
        for (int mi = 0; mi < 4; mi++)
            #pragma unroll
            for (int ni = 0; ni < 4; ni++) { dh[mi][ni][0] = 0u; dh[mi][ni][1] = 0u; }

        uint32_t bBase = sb + OFF_W(s) + bRowOff;
        uint32_t aChunk0 = (uint32_t)(ke * 8);

        #pragma unroll
        for (int kk = 0; kk < 4; kk++) {
            uint32_t aswz = (((aChunk0 + (uint32_t)(kk << 1) + aHi) ^ x7) << 4);
            uint32_t bswz = ((((uint32_t)(kk << 1) + bHi) ^ x7) << 4);
            uint32_t a[4][4], b0[4], b1[4];
            #pragma unroll
            for (int mi = 0; mi < 4; mi++)
                ldsm_x4(a[mi][0], a[mi][1], a[mi][2], a[mi][3], aRow[mi] + aswz);
            ldsm_x4(b0[0], b0[1], b0[2], b0[3], bBase + bswz);
            ldsm_x4(b1[0], b1[1], b1[2], b1[3], bBase + 16 * 128 + bswz);
            #pragma unroll
            for (int mi = 0; mi < 4; mi++) {
                mma16816h(dh[mi][0], a[mi], b0 + 0);
                mma16816h(dh[mi][1], a[mi], b0 + 2);
                mma16816h(dh[mi][2], a[mi], b1 + 0);
                mma16816h(dh[mi][3], a[mi], b1 + 2);
            }
        }

        // fold fp16 slab sums into fp32 accumulators
        #pragma unroll
        for (int mi = 0; mi < 4; mi++)
            #pragma unroll
            for (int ni = 0; ni < 4; ni++) {
                float2 lo = __half22float2(*(__half2*)&dh[mi][ni][0]);
                float2 hi = __half22float2(*(__half2*)&dh[mi][ni][1]);
                dacc[mi][ni][0] += lo.x;
                dacc[mi][ni][1] += lo.y;
                dacc[mi][ni][2] += hi.x;
                dacc[mi][ni][3] += hi.y;
            }

        if (ke == 7) {
            int ncol = (st >> 3) * 128 + n0 + (lane & 3) * 2;
            #pragma unroll
            for (int ni = 0; ni < 4; ni++) {
                int c0 = ncol + ni * 8, c1 = c0 + 1;
                float bb0 = b2s[c0], bb1 = b2s[c1];
                float ww0 = w3s[c0], ww1 = w3s[c1];
                #pragma unroll
                for (int mi = 0; mi < 4; mi++) {
                    rowacc[mi][0] = fmaf(fmaxf(dacc[mi][ni][0] + bb0, 0.f), ww0, rowacc[mi][0]);
                    rowacc[mi][0] = fmaf(fmaxf(dacc[mi][ni][1] + bb1, 0.f), ww1, rowacc[mi][0]);
                    rowacc[mi][1] = fmaf(fmaxf(dacc[mi][ni][2] + bb0, 0.f), ww0, rowacc[mi][1]);
                    rowacc[mi][1] = fmaf(fmaxf(dacc[mi][ni][3] + bb1, 0.f), ww1, rowacc[mi][1]);
                }
            }
        }

        // last warp to finish this step issues the refetch into this slab
        if (lane == 0) {
            int old;
            asm volatile("atom.shared.add.s32 %0, [%1], 1;"
                         : "=r"(old) : "r"(sb + OFF_MB + 16 + s * 4) : "memory");
            if ((old & 3) == 3 && st + 2 < 32) {
                MBAR_EXPECT_TX(sb + OFF_MB + s * 8, 16384u);
                bulk_g2s(sb + OFF_W(s), g_Wsw + (size_t)(st + 2) * 16384, 16384u,
                         sb + OFF_MB + s * 8);
            }
        }
    }

    // ---- reduce across 4 lanes sharing each row, then across 4 n-warps ----
    #pragma unroll
    for (int mi = 0; mi < 4; mi++)
        #pragma unroll
        for (int rh = 0; rh < 2; rh++) {
            rowacc[mi][rh] += __shfl_xor_sync(0xFFFFFFFFu, rowacc[mi][rh], 1);
            rowacc[mi][rh] += __shfl_xor_sync(0xFFFFFFFFu, rowacc[mi][rh], 2);
        }

    __syncthreads();   // all warps out of the main loop before reusing W(0)

    float* part = (float*)(smem + OFF_W(0));  // reuse: [64][4]
    if ((lane & 3) == 0) {
        int g = lane >> 2;
        #pragma unroll
        for (int mi = 0; mi < 4; mi++)
            #pragma unroll
            for (int rh = 0; rh < 2; rh++) {
                int m = mi * 16 + rh * 8 + g;
                part[m * 4 + wid] = rowacc[mi][rh];
            }
    }
    __syncthreads();

    if (tid < 64) {
        float res = part[tid * 4 + 0] + part[tid * 4 + 1] +
                    part[tid * 4 + 2] + part[tid * 4 + 3] + b3g[0];
        int i = i0 + (tid >> 3);
        int j = j0 + (tid & 7);
        out[i * BB + j] = res;
    }
}

// ============================================================================
// Host launcher
// ============================================================================
extern "C" void kernel_launch(void* const* d_in, const int* in_sizes, int n_in,
                              void* d_out, int out_size) {
    const float* x  = (const float*)d_in[0];
    const float* y  = (const float*)d_in[1];
    const float* W1 = (const float*)d_in[2];
    const float* b1 = (const float*)d_in[3];
    const float* W2 = (const float*)d_in[4];
    const float* b2 = (const float*)d_in[5];
    const float* W3 = (const float*)d_in[6];
    const float* b3 = (const float*)d_in[7];
    float* out = (float*)d_out;

    cudaFuncSetAttribute(k_main, cudaFuncAttributeMaxDynamicSharedMemorySize, SMEM_BYTES);

    k_prep<<<1024, 256>>>(x, y, W1, b1, W2);
    k_main<<<4096, 128, SMEM_BYTES>>>(b2, W3, b3, out);
}

// round 11
// speedup vs baseline: 1.1398x; 1.1398x over previous
#include <cuda_runtime.h>
#include <cuda_fp16.h>
#include <cstdint>

// ============================================================================
// out[i,j] = w3 . relu(W2 . relu(hx_i + hy_j + b1) + b2) + b3
// B = 512, H = 512, DX = DY = 128
// ============================================================================
#define BB 512
#define HH 512

__device__ __align__(128)  float  g_hx[BB * HH];           // x@W1[:, :128]^T + b1
__device__ __align__(128)  float  g_hy[BB * HH];           // y@W1[:, 128:]^T
// W2 fp16, pre-swizzled step-major: 32 steps (nc*8 + ke) of 16KB.
// slab: row n_local (0..127) * 128B; 16B chunk c at ((c ^ (n_local&7))<<4).
__device__ __align__(1024) unsigned char g_Wsw[HH * HH * 2];

// k_main SMEM layout (dynamic, bytes)
#define OFF_A    0                         // 64 rows x 1024B (fp16, swizzled)
#define OFF_W(s) (65536 + (s) * 16384)     // 2 x 16KB W slabs
#define OFF_B2   98304                     // 512 f32
#define OFF_W3   100352                    // 512 f32
#define OFF_MB   102400                    // 2 mbarriers (16B) + 2 counters (8B)
#define SMEM_BYTES 102528

static __device__ __forceinline__ uint32_t smem_u32(const void* p) {
    uint32_t a;
    asm("{ .reg .u64 t; cvta.to.shared.u64 t, %1; cvt.u32.u64 %0, t; }" : "=r"(a) : "l"(p));
    return a;
}
#define MBAR_INIT(addr, cnt) \
    asm volatile("mbarrier.init.shared.b64 [%0], %1;" :: "r"(addr), "r"(cnt) : "memory")
#define MBAR_EXPECT_TX(addr, bytes) \
    asm volatile("mbarrier.arrive.expect_tx.shared.b64 _, [%0], %1;" :: "r"(addr), "r"(bytes) : "memory")
#define MBAR_WAIT(addr, ph) do {                                                \
    uint32_t _m = (addr), _p = (ph), _d;                                        \
    asm volatile("{\n\t.reg .pred p;\n\t"                                       \
        "mbarrier.try_wait.parity.acquire.cta.shared::cta.b64 p, [%1], %2;\n\t" \
        "selp.b32 %0, 1, 0, p;\n\t}" : "=r"(_d) : "r"(_m), "r"(_p) : "memory"); \
    if (!_d) {                                                                  \
        asm volatile("{\n\t.reg .pred P;\n\tWL%=:\n\t"                          \
            "mbarrier.try_wait.parity.acquire.cta.shared::cta.b64 P, [%0], %1, 0x989680;\n\t" \
            "@P bra.uni WD%=;\n\tbra.uni WL%=;\n\tWD%=:\n\t}"                   \
            :: "r"(_m), "r"(_p) : "memory");                                    \
    }                                                                           \
} while (0)
static __device__ __forceinline__ void bulk_g2s(uint32_t dst, const void* src,
                                                uint32_t bytes, uint32_t mbar) {
    asm volatile(
        "cp.async.bulk.shared::cluster.global.mbarrier::complete_tx::bytes [%0], [%1], %2, [%3];"
        :: "r"(dst), "l"(src), "r"(bytes), "r"(mbar) : "memory");
}
static __device__ __forceinline__ void ldsm_x4(uint32_t& r0, uint32_t& r1, uint32_t& r2,
                                               uint32_t& r3, uint32_t addr) {
    asm volatile("ldmatrix.sync.aligned.m8n8.x4.shared.b16 {%0,%1,%2,%3}, [%4];"
                 : "=r"(r0), "=r"(r1), "=r"(r2), "=r"(r3) : "r"(addr));
}
static __device__ __forceinline__ void mma16816(float* d, const uint32_t* a, const uint32_t* b) {
    asm volatile(
        "mma.sync.aligned.m16n8k16.row.col.f32.f16.f16.f32 "
        "{%0,%1,%2,%3}, {%4,%5,%6,%7}, {%8,%9}, {%0,%1,%2,%3};"
        : "+f"(d[0]), "+f"(d[1]), "+f"(d[2]), "+f"(d[3])
        : "r"(a[0]), "r"(a[1]), "r"(a[2]), "r"(a[3]), "r"(b[0]), "r"(b[1]));
}

// ============================================================================
// Kernel 1: prep = first linear (blocks 0..511) + W2 quant/swizzle (512..1023)
// ============================================================================
__global__ void __launch_bounds__(256) k_prep(const float* __restrict__ x,
                                              const float* __restrict__ y,
                                              const float* __restrict__ W1,
                                              const float* __restrict__ b1,
                                              const float* __restrict__ W2) {
    int b = blockIdx.x;
    if (b >= 512) {
        // quant: 2 consecutive h per thread; layout = 32 steps of 16KB
        int idx = ((b - 512) * 256 + threadIdx.x) * 2;
        int n = idx >> 9, h = idx & 511;
        int nc = n >> 7, n_local = n & 127;
        int ke = h >> 6, k_local = h & 63;
        int step = nc * 8 + ke;
        uint32_t c = (uint32_t)(k_local >> 3);
        uint32_t off = (uint32_t)n_local * 128 +
                       ((c ^ (uint32_t)(n_local & 7)) << 4) + (uint32_t)(k_local & 7) * 2;
        float2 v = *(const float2*)(W2 + (size_t)n * HH + h);
        __half2 hv;
        hv.x = __float2half_rn(v.x);
        hv.y = __float2half_rn(v.y);
        *(uint32_t*)(g_Wsw + (size_t)step * 16384 + off) = *(uint32_t*)&hv;
        return;
    }
    __shared__ float xs_t[128][33];
    __shared__ float ws[32][128];
    int path = b >> 8;
    int rem = b & 255;
    int i0 = (rem & 15) * 32, h0 = (rem >> 4) * 32;
    const float* src = path ? y : x;
    int colOff = path ? 128 : 0;

    for (int v = threadIdx.x; v < 32 * 128; v += 256) {
        int i = v >> 7, d = v & 127;
        xs_t[d][i] = src[(i0 + i) * 128 + d];
    }
    for (int v = threadIdx.x; v < 32 * 32; v += 256) {
        int r = v >> 5, c4 = v & 31;
        ((float4*)&ws[r][0])[c4] = ((const float4*)&W1[(h0 + r) * 256 + colOff])[c4];
    }
    __syncthreads();

    int ti = threadIdx.x & 31, th = threadIdx.x >> 5;
    float acc0 = 0.f, acc1 = 0.f, acc2 = 0.f, acc3 = 0.f;
    #pragma unroll 4
    for (int d = 0; d < 128; d++) {
        float xv = xs_t[d][ti];
        acc0 = fmaf(xv, ws[th * 4 + 0][d], acc0);
        acc1 = fmaf(xv, ws[th * 4 + 1][d], acc1);
        acc2 = fmaf(xv, ws[th * 4 + 2][d], acc2);
        acc3 = fmaf(xv, ws[th * 4 + 3][d], acc3);
    }
    float* dst = path ? g_hy : g_hx;
    int i = i0 + ti;
    int hb = h0 + th * 4;
    float a0 = path ? 0.f : b1[hb + 0];
    float a1 = path ? 0.f : b1[hb + 1];
    float a2 = path ? 0.f : b1[hb + 2];
    float a3 = path ? 0.f : b1[hb + 3];
    dst[i * HH + hb + 0] = acc0 + a0;
    dst[i * HH + hb + 1] = acc1 + a1;
    dst[i * HH + hb + 2] = acc2 + a2;
    dst[i * HH + hb + 3] = acc3 + a3;
}

// ============================================================================
// Kernel 2: main pair-GEMM + fused epilogue.  grid 4096, block 256 (8 warps)
//   CTA tile: 64 pairs (8i x 8j), ~100KB SMEM -> 2 CTAs/SM = 16 warps/SM
//   = 4 warps/SMSP (latency hiding).  32 steps of 16KB W (cp.async.bulk,
//   2-deep, last-warp refetch).  Warp grid 2m x 4n, warp tile m32 x n32,
//   fp32 accumulators.
// ============================================================================
__global__ void __launch_bounds__(256, 2) k_main(const float* __restrict__ b2g,
                                                 const float* __restrict__ w3g,
                                                 const float* __restrict__ b3g,
                                                 float* __restrict__ out) {
    extern __shared__ __align__(1024) unsigned char smem[];
    uint32_t sb = smem_u32(smem);
    int tid = threadIdx.x, wid = tid >> 5, lane = tid & 31;
    int t = blockIdx.x;
    int i0 = (t >> 6) * 8, j0 = (t & 63) * 8;

    float* b2s = (float*)(smem + OFF_B2);
    float* w3s = (float*)(smem + OFF_W3);
    int* wcnt = (int*)(smem + OFF_MB + 16);

    // ---- init mbarriers/counters + kick off first two W slabs ----
    if (tid == 0) {
        MBAR_INIT(sb + OFF_MB + 0, 1);
        MBAR_INIT(sb + OFF_MB + 8, 1);
        wcnt[0] = 0;
        wcnt[1] = 0;
        asm volatile("fence.proxy.async.shared::cta;" ::: "memory");
        MBAR_EXPECT_TX(sb + OFF_MB + 0, 16384u);
        bulk_g2s(sb + OFF_W(0), g_Wsw + 0 * 16384, 16384u, sb + OFF_MB + 0);
        MBAR_EXPECT_TX(sb + OFF_MB + 8, 16384u);
        bulk_g2s(sb + OFF_W(1), g_Wsw + 1 * 16384, 16384u, sb + OFF_MB + 8);
    }

    // ---- b2 / w3 to SMEM ----
    for (int v = tid; v < 512; v += 256) {
        b2s[v] = b2g[v];
        w3s[v] = w3g[v];
    }

    // ---- build A = relu(hx_i + hy_j) fp16 (register-blocked, 1 col/thread) ----
    {
        int kk = tid;  // half2 column 0..255
        float2 hyv[8];
        #pragma unroll
        for (int j = 0; j < 8; j++)
            hyv[j] = ((const float2*)(g_hy + (j0 + j) * HH))[kk];
        uint32_t base = sb + OFF_A + (uint32_t)(kk & 3) * 4;
        uint32_t chunk = (uint32_t)(kk >> 2);
        #pragma unroll
        for (int ig = 0; ig < 8; ig++) {
            float2 hx2 = ((const float2*)(g_hx + (i0 + ig) * HH))[kk];
            #pragma unroll
            for (int j = 0; j < 8; j++) {
                float v0 = fmaxf(hx2.x + hyv[j].x, 0.f);
                float v1 = fmaxf(hx2.y + hyv[j].y, 0.f);
                __half2 hv;
                hv.x = __float2half_rn(v0);
                hv.y = __float2half_rn(v1);
                uint32_t p = (uint32_t)(ig * 8 + j);
                uint32_t addr = base + p * 1024 + ((chunk ^ (p & 7)) << 4);
                asm volatile("st.shared.b32 [%0], %1;"
                             :: "r"(addr), "r"(*(uint32_t*)&hv) : "memory");
            }
        }
    }
    __syncthreads();   // A ready; mbarrier/counter inits visible

    // ---- per-warp geometry: warp grid 2m x 4n, warp tile m32 x n32 ----
    int wm = wid & 1;           // m0 = wm*32
    int wn = wid >> 1;          // 0..3 -> n0 = wn*32 within 128-chunk
    int m0 = wm * 32, n0 = wn * 32;

    uint32_t x7 = (uint32_t)(lane & 7);
    uint32_t aHi = (uint32_t)(lane >> 4);
    uint32_t aRow[2];
    #pragma unroll
    for (int mi = 0; mi < 2; mi++)
        aRow[mi] = sb + OFF_A + (uint32_t)(m0 + mi * 16 + (lane & 15)) * 1024;
    uint32_t bRowOff = (uint32_t)(n0 + (lane & 7) + ((lane >> 4) << 3)) * 128;
    uint32_t bHi = (uint32_t)((lane >> 3) & 1);

    float d[2][4][4];                 // [mi][ni][q]  fp32 persistent per n-chunk
    float rowacc[2][2];               // [mi][row half]
    #pragma unroll
    for (int mi = 0; mi < 2; mi++) { rowacc[mi][0] = 0.f; rowacc[mi][1] = 0.f; }

    #pragma unroll 1
    for (int st = 0; st < 32; st++) {
        int s = st & 1, ke = st & 7;
        MBAR_WAIT(sb + OFF_MB + s * 8, (st >> 1) & 1);

        if (ke == 0) {
            #pragma unroll
            for (int mi = 0; mi < 2; mi++)
                #pragma unroll
                for (int ni = 0; ni < 4; ni++)
                    #pragma unroll
                    for (int q = 0; q < 4; q++) d[mi][ni][q] = 0.f;
        }

        uint32_t bBase = sb + OFF_W(s) + bRowOff;
        uint32_t aChunk0 = (uint32_t)(ke * 8);

        #pragma unroll
        for (int kk = 0; kk < 4; kk++) {
            uint32_t aswz = (((aChunk0 + (uint32_t)(kk << 1) + aHi) ^ x7) << 4);
            uint32_t bswz = ((((uint32_t)(kk << 1) + bHi) ^ x7) << 4);
            uint32_t a[2][4], b0[4], b1[4];
            #pragma unroll
            for (int mi = 0; mi < 2; mi++)
                ldsm_x4(a[mi][0], a[mi][1], a[mi][2], a[mi][3], aRow[mi] + aswz);
            ldsm_x4(b0[0], b0[1], b0[2], b0[3], bBase + bswz);
            ldsm_x4(b1[0], b1[1], b1[2], b1[3], bBase + 16 * 128 + bswz);
            #pragma unroll
            for (int mi = 0; mi < 2; mi++) {
                mma16816(d[mi][0], a[mi], b0 + 0);
                mma16816(d[mi][1], a[mi], b0 + 2);
                mma16816(d[mi][2], a[mi], b1 + 0);
                mma16816(d[mi][3], a[mi], b1 + 2);
            }
        }

        if (ke == 7) {
            // fold: rowacc += sum_n relu(D + b2[n]) * w3[n]
            int ncol = (st >> 3) * 128 + n0 + (lane & 3) * 2;
            #pragma unroll
            for (int ni = 0; ni < 4; ni++) {
                int c0 = ncol + ni * 8, c1 = c0 + 1;
                float bb0 = b2s[c0], bb1 = b2s[c1];
                float ww0 = w3s[c0], ww1 = w3s[c1];
                #pragma unroll
                for (int mi = 0; mi < 2; mi++) {
                    rowacc[mi][0] = fmaf(fmaxf(d[mi][ni][0] + bb0, 0.f), ww0, rowacc[mi][0]);
                    rowacc[mi][0] = fmaf(fmaxf(d[mi][ni][1] + bb1, 0.f), ww1, rowacc[mi][0]);
                    rowacc[mi][1] = fmaf(fmaxf(d[mi][ni][2] + bb0, 0.f), ww0, rowacc[mi][1]);
                    rowacc[mi][1] = fmaf(fmaxf(d[mi][ni][3] + bb1, 0.f), ww1, rowacc[mi][1]);
                }
            }
        }

        // last warp to finish this step issues the refetch into this slab
        if (lane == 0) {
            int old;
            asm volatile("atom.shared.add.s32 %0, [%1], 1;"
                         : "=r"(old) : "r"(sb + OFF_MB + 16 + s * 4) : "memory");
            if ((old & 7) == 7 && st + 2 < 32) {
                MBAR_EXPECT_TX(sb + OFF_MB + s * 8, 16384u);
                bulk_g2s(sb + OFF_W(s), g_Wsw + (size_t)(st + 2) * 16384, 16384u,
                         sb + OFF_MB + s * 8);
            }
        }
    }

    // ---- reduce across 4 lanes sharing each row, then across 4 n-warps ----
    #pragma unroll
    for (int mi = 0; mi < 2; mi++)
        #pragma unroll
        for (int rh = 0; rh < 2; rh++) {
            rowacc[mi][rh] += __shfl_xor_sync(0xFFFFFFFFu, rowacc[mi][rh], 1);
            rowacc[mi][rh] += __shfl_xor_sync(0xFFFFFFFFu, rowacc[mi][rh], 2);
        }

    __syncthreads();   // all warps out of the main loop before reusing W(0)

    float* part = (float*)(smem + OFF_W(0));  // reuse: [64][4]
    if ((lane & 3) == 0) {
        int g = lane >> 2;
        #pragma unroll
        for (int mi = 0; mi < 2; mi++)
            #pragma unroll
            for (int rh = 0; rh < 2; rh++) {
                int m = m0 + mi * 16 + rh * 8 + g;
                part[m * 4 + wn] = rowacc[mi][rh];
            }
    }
    __syncthreads();

    if (tid < 64) {
        float res = part[tid * 4 + 0] + part[tid * 4 + 1] +
                    part[tid * 4 + 2] + part[tid * 4 + 3] + b3g[0];
        int i = i0 + (tid >> 3);
        int j = j0 + (tid & 7);
        out[i * BB + j] = res;
    }
}

// ============================================================================
// Host launcher
// ============================================================================
extern "C" void kernel_launch(void* const* d_in, const int* in_sizes, int n_in,
                              void* d_out, int out_size) {
    const float* x  = (const float*)d_in[0];
    const float* y  = (const float*)d_in[1];
    const float* W1 = (const float*)d_in[2];
    const float* b1 = (const float*)d_in[3];
    const float* W2 = (const float*)d_in[4];
    const float* b2 = (const float*)d_in[5];
    const float* W3 = (const float*)d_in[6];
    const float* b3 = (const float*)d_in[7];
    float* out = (float*)d_out;

    cudaFuncSetAttribute(k_main, cudaFuncAttributeMaxDynamicSharedMemorySize, SMEM_BYTES);

    k_prep<<<1024, 256>>>(x, y, W1, b1, W2);
    k_main<<<4096, 256, SMEM_BYTES>>>(b2, W3, b3, out);
}

// round 12
// speedup vs baseline: 1.2007x; 1.0534x over previous
#include <cuda_runtime.h>
#include <cuda_fp16.h>
#include <cstdint>

// ============================================================================
// out[i,j] = w3 . relu(W2 . relu(hx_i + hy_j + b1) + b2) + b3
// B = 512, H = 512, DX = DY = 128
// ============================================================================
#define BB 512
#define HH 512
#define NCTA 296          // persistent CTAs, 2 per SM
#define NTILE 4096

__device__ __align__(128)  float  g_hx[BB * HH];           // x@W1[:, :128]^T + b1
__device__ __align__(128)  float  g_hy[BB * HH];           // y@W1[:, 128:]^T
// W2 fp16, pre-swizzled step-major: 32 steps (nc*8 + ke) of 16KB.
// slab: row n_local (0..127) * 128B; 16B chunk c at ((c ^ (n_local&7))<<4).
__device__ __align__(1024) unsigned char g_Wsw[HH * HH * 2];

// k_main SMEM layout (dynamic, bytes)
#define OFF_A    0                         // 64 rows x 1024B (fp16, swizzled)
#define OFF_W(s) (65536 + (s) * 16384)     // 2 x 16KB W slabs
#define OFF_B2   98304                     // 512 f32
#define OFF_W3   100352                    // 512 f32
#define OFF_MB   102400                    // 2 mbarriers (16B) + 2 counters (8B)
#define OFF_PART 102432                    // 64 x 4 f32 epilogue scratch
#define SMEM_BYTES 103456

static __device__ __forceinline__ uint32_t smem_u32(const void* p) {
    uint32_t a;
    asm("{ .reg .u64 t; cvta.to.shared.u64 t, %1; cvt.u32.u64 %0, t; }" : "=r"(a) : "l"(p));
    return a;
}
#define MBAR_INIT(addr, cnt) \
    asm volatile("mbarrier.init.shared.b64 [%0], %1;" :: "r"(addr), "r"(cnt) : "memory")
#define MBAR_EXPECT_TX(addr, bytes) \
    asm volatile("mbarrier.arrive.expect_tx.shared.b64 _, [%0], %1;" :: "r"(addr), "r"(bytes) : "memory")
#define MBAR_WAIT(addr, ph) do {                                                \
    uint32_t _m = (addr), _p = (ph), _d;                                        \
    asm volatile("{\n\t.reg .pred p;\n\t"                                       \
        "mbarrier.try_wait.parity.acquire.cta.shared::cta.b64 p, [%1], %2;\n\t" \
        "selp.b32 %0, 1, 0, p;\n\t}" : "=r"(_d) : "r"(_m), "r"(_p) : "memory"); \
    if (!_d) {                                                                  \
        asm volatile("{\n\t.reg .pred P;\n\tWL%=:\n\t"                          \
            "mbarrier.try_wait.parity.acquire.cta.shared::cta.b64 P, [%0], %1, 0x989680;\n\t" \
            "@P bra.uni WD%=;\n\tbra.uni WL%=;\n\tWD%=:\n\t}"                   \
            :: "r"(_m), "r"(_p) : "memory");                                    \
    }                                                                           \
} while (0)
static __device__ __forceinline__ void bulk_g2s(uint32_t dst, const void* src,
                                                uint32_t bytes, uint32_t mbar) {
    asm volatile(
        "cp.async.bulk.shared::cluster.global.mbarrier::complete_tx::bytes [%0], [%1], %2, [%3];"
        :: "r"(dst), "l"(src), "r"(bytes), "r"(mbar) : "memory");
}
static __device__ __forceinline__ void ldsm_x4(uint32_t& r0, uint32_t& r1, uint32_t& r2,
                                               uint32_t& r3, uint32_t addr) {
    asm volatile("ldmatrix.sync.aligned.m8n8.x4.shared.b16 {%0,%1,%2,%3}, [%4];"
                 : "=r"(r0), "=r"(r1), "=r"(r2), "=r"(r3) : "r"(addr));
}
static __device__ __forceinline__ void mma16816(float* d, const uint32_t* a, const uint32_t* b) {
    asm volatile(
        "mma.sync.aligned.m16n8k16.row.col.f32.f16.f16.f32 "
        "{%0,%1,%2,%3}, {%4,%5,%6,%7}, {%8,%9}, {%0,%1,%2,%3};"
        : "+f"(d[0]), "+f"(d[1]), "+f"(d[2]), "+f"(d[3])
        : "r"(a[0]), "r"(a[1]), "r"(a[2]), "r"(a[3]), "r"(b[0]), "r"(b[1]));
}

// ============================================================================
// Kernel 1: prep = first linear (blocks 0..511) + W2 quant/swizzle (512..1023)
// ============================================================================
__global__ void __launch_bounds__(256) k_prep(const float* __restrict__ x,
                                              const float* __restrict__ y,
                                              const float* __restrict__ W1,
                                              const float* __restrict__ b1,
                                              const float* __restrict__ W2) {
    int b = blockIdx.x;
    if (b >= 512) {
        // quant: 2 consecutive h per thread; layout = 32 steps of 16KB
        int idx = ((b - 512) * 256 + threadIdx.x) * 2;
        int n = idx >> 9, h = idx & 511;
        int nc = n >> 7, n_local = n & 127;
        int ke = h >> 6, k_local = h & 63;
        int step = nc * 8 + ke;
        uint32_t c = (uint32_t)(k_local >> 3);
        uint32_t off = (uint32_t)n_local * 128 +
                       ((c ^ (uint32_t)(n_local & 7)) << 4) + (uint32_t)(k_local & 7) * 2;
        float2 v = *(const float2*)(W2 + (size_t)n * HH + h);
        __half2 hv;
        hv.x = __float2half_rn(v.x);
        hv.y = __float2half_rn(v.y);
        *(uint32_t*)(g_Wsw + (size_t)step * 16384 + off) = *(uint32_t*)&hv;
        return;
    }
    __shared__ float xs_t[128][33];
    __shared__ float ws[32][128];
    int path = b >> 8;
    int rem = b & 255;
    int i0 = (rem & 15) * 32, h0 = (rem >> 4) * 32;
    const float* src = path ? y : x;
    int colOff = path ? 128 : 0;

    for (int v = threadIdx.x; v < 32 * 128; v += 256) {
        int i = v >> 7, d = v & 127;
        xs_t[d][i] = src[(i0 + i) * 128 + d];
    }
    for (int v = threadIdx.x; v < 32 * 32; v += 256) {
        int r = v >> 5, c4 = v & 31;
        ((float4*)&ws[r][0])[c4] = ((const float4*)&W1[(h0 + r) * 256 + colOff])[c4];
    }
    __syncthreads();

    int ti = threadIdx.x & 31, th = threadIdx.x >> 5;
    float acc0 = 0.f, acc1 = 0.f, acc2 = 0.f, acc3 = 0.f;
    #pragma unroll 4
    for (int d = 0; d < 128; d++) {
        float xv = xs_t[d][ti];
        acc0 = fmaf(xv, ws[th * 4 + 0][d], acc0);
        acc1 = fmaf(xv, ws[th * 4 + 1][d], acc1);
        acc2 = fmaf(xv, ws[th * 4 + 2][d], acc2);
        acc3 = fmaf(xv, ws[th * 4 + 3][d], acc3);
    }
    float* dst = path ? g_hy : g_hx;
    int i = i0 + ti;
    int hb = h0 + th * 4;
    float a0 = path ? 0.f : b1[hb + 0];
    float a1 = path ? 0.f : b1[hb + 1];
    float a2 = path ? 0.f : b1[hb + 2];
    float a3 = path ? 0.f : b1[hb + 3];
    dst[i * HH + hb + 0] = acc0 + a0;
    dst[i * HH + hb + 1] = acc1 + a1;
    dst[i * HH + hb + 2] = acc2 + a2;
    dst[i * HH + hb + 3] = acc3 + a3;
}

// ============================================================================
// Kernel 2: persistent main pair-GEMM + fused epilogue.
//   grid 296 (2 CTAs/SM), block 128 (4 warps).  Each CTA loops over tiles
//   t = bid, bid+296, ...  Per tile: 64 pairs (8i x 8j), 32 steps of 16KB W.
//   W double-buffer pipeline runs CONTINUOUSLY across tiles (global step gst);
//   tile boundary costs only A-rebuild + 2 barriers.  Warp tile m64 x n32.
// ============================================================================
__global__ void __launch_bounds__(128, 2) k_main(const float* __restrict__ b2g,
                                                 const float* __restrict__ w3g,
                                                 const float* __restrict__ b3g,
                                                 float* __restrict__ out) {
    extern __shared__ __align__(1024) unsigned char smem[];
    uint32_t sb = smem_u32(smem);
    int tid = threadIdx.x, wid = tid >> 5, lane = tid & 31;

    float* b2s = (float*)(smem + OFF_B2);
    float* w3s = (float*)(smem + OFF_W3);
    int* wcnt = (int*)(smem + OFF_MB + 16);
    float* part = (float*)(smem + OFF_PART);

    // tiles handled by this CTA
    int ntiles = 0;
    for (int t = blockIdx.x; t < NTILE; t += NCTA) ntiles++;
    int total_gst = ntiles * 32;

    // ---- one-time init: mbarriers/counters + first two W slabs + b2/w3 ----
    if (tid == 0) {
        MBAR_INIT(sb + OFF_MB + 0, 1);
        MBAR_INIT(sb + OFF_MB + 8, 1);
        wcnt[0] = 0;
        wcnt[1] = 0;
        asm volatile("fence.proxy.async.shared::cta;" ::: "memory");
        MBAR_EXPECT_TX(sb + OFF_MB + 0, 16384u);
        bulk_g2s(sb + OFF_W(0), g_Wsw + 0 * 16384, 16384u, sb + OFF_MB + 0);
        MBAR_EXPECT_TX(sb + OFF_MB + 8, 16384u);
        bulk_g2s(sb + OFF_W(1), g_Wsw + 1 * 16384, 16384u, sb + OFF_MB + 8);
    }
    for (int v = tid; v < 512; v += 128) {
        b2s[v] = b2g[v];
        w3s[v] = w3g[v];
    }
    float b3v = b3g[0];

    // ---- lane geometry (tile-independent): warp tile m64 x n32 ----
    int n0 = wid * 32;
    uint32_t x7 = (uint32_t)(lane & 7);
    uint32_t aHi = (uint32_t)(lane >> 4);
    uint32_t aRow[4];
    #pragma unroll
    for (int mi = 0; mi < 4; mi++)
        aRow[mi] = sb + OFF_A + (uint32_t)(mi * 16 + (lane & 15)) * 1024;
    uint32_t bRowOff = (uint32_t)(n0 + (lane & 7) + ((lane >> 4) << 3)) * 128;
    uint32_t bHi = (uint32_t)((lane >> 3) & 1);

    int gst = 0;

    #pragma unroll 1
    for (int t = blockIdx.x; t < NTILE; t += NCTA) {
        int i0 = (t >> 6) * 8, j0 = (t & 63) * 8;

        // ---- tile boundary: all warps done with previous A ----
        __syncthreads();

        // ---- build A = relu(hx_i + hy_j) fp16 (register-blocked) ----
        #pragma unroll
        for (int hf = 0; hf < 2; hf++) {
            int kk = tid + hf * 128;  // half2 column
            float2 hyv[8];
            #pragma unroll
            for (int j = 0; j < 8; j++)
                hyv[j] = ((const float2*)(g_hy + (j0 + j) * HH))[kk];
            uint32_t base = sb + OFF_A + (uint32_t)(kk & 3) * 4;
            uint32_t chunk = (uint32_t)(kk >> 2);
            #pragma unroll
            for (int ig = 0; ig < 8; ig++) {
                float2 hx2 = ((const float2*)(g_hx + (i0 + ig) * HH))[kk];
                #pragma unroll
                for (int j = 0; j < 8; j++) {
                    float v0 = fmaxf(hx2.x + hyv[j].x, 0.f);
                    float v1 = fmaxf(hx2.y + hyv[j].y, 0.f);
                    __half2 hv;
                    hv.x = __float2half_rn(v0);
                    hv.y = __float2half_rn(v1);
                    uint32_t p = (uint32_t)(ig * 8 + j);
                    uint32_t addr = base + p * 1024 + ((chunk ^ (p & 7)) << 4);
                    asm volatile("st.shared.b32 [%0], %1;"
                                 :: "r"(addr), "r"(*(uint32_t*)&hv) : "memory");
                }
            }
        }
        __syncthreads();   // A visible (also covers one-time init on first tile)

        float d[4][4][4];                 // [mi][ni][q]
        float rowacc[4][2];               // [mi][row half]
        #pragma unroll
        for (int mi = 0; mi < 4; mi++) { rowacc[mi][0] = 0.f; rowacc[mi][1] = 0.f; }

        #pragma unroll 1
        for (int st = 0; st < 32; st++, gst++) {
            int s = gst & 1, ke = st & 7;
            MBAR_WAIT(sb + OFF_MB + s * 8, (gst >> 1) & 1);

            if (ke == 0) {
                #pragma unroll
                for (int mi = 0; mi < 4; mi++)
                    #pragma unroll
                    for (int ni = 0; ni < 4; ni++)
                        #pragma unroll
                        for (int q = 0; q < 4; q++) d[mi][ni][q] = 0.f;
            }

            uint32_t bBase = sb + OFF_W(s) + bRowOff;
            uint32_t aChunk0 = (uint32_t)(ke * 8);

            #pragma unroll
            for (int kk = 0; kk < 4; kk++) {
                uint32_t aswz = (((aChunk0 + (uint32_t)(kk << 1) + aHi) ^ x7) << 4);
                uint32_t bswz = ((((uint32_t)(kk << 1) + bHi) ^ x7) << 4);
                uint32_t a[4][4], b0[4], b1[4];
                #pragma unroll
                for (int mi = 0; mi < 4; mi++)
                    ldsm_x4(a[mi][0], a[mi][1], a[mi][2], a[mi][3], aRow[mi] + aswz);
                ldsm_x4(b0[0], b0[1], b0[2], b0[3], bBase + bswz);
                ldsm_x4(b1[0], b1[1], b1[2], b1[3], bBase + 16 * 128 + bswz);
                #pragma unroll
                for (int mi = 0; mi < 4; mi++) {
                    mma16816(d[mi][0], a[mi], b0 + 0);
                    mma16816(d[mi][1], a[mi], b0 + 2);
                    mma16816(d[mi][2], a[mi], b1 + 0);
                    mma16816(d[mi][3], a[mi], b1 + 2);
                }
            }

            if (ke == 7) {
                // fold: rowacc += sum_n relu(D + b2[n]) * w3[n]
                int ncol = (st >> 3) * 128 + n0 + (lane & 3) * 2;
                #pragma unroll
                for (int ni = 0; ni < 4; ni++) {
                    int c0 = ncol + ni * 8, c1 = c0 + 1;
                    float bb0 = b2s[c0], bb1 = b2s[c1];
                    float ww0 = w3s[c0], ww1 = w3s[c1];
                    #pragma unroll
                    for (int mi = 0; mi < 4; mi++) {
                        rowacc[mi][0] = fmaf(fmaxf(d[mi][ni][0] + bb0, 0.f), ww0, rowacc[mi][0]);
                        rowacc[mi][0] = fmaf(fmaxf(d[mi][ni][1] + bb1, 0.f), ww1, rowacc[mi][0]);
                        rowacc[mi][1] = fmaf(fmaxf(d[mi][ni][2] + bb0, 0.f), ww0, rowacc[mi][1]);
                        rowacc[mi][1] = fmaf(fmaxf(d[mi][ni][3] + bb1, 0.f), ww1, rowacc[mi][1]);
                    }
                }
            }

            // last warp to finish this step issues the refetch into this slab
            if (lane == 0) {
                int old;
                asm volatile("atom.shared.add.s32 %0, [%1], 1;"
                             : "=r"(old) : "r"(sb + OFF_MB + 16 + s * 4) : "memory");
                if ((old & 3) == 3 && gst + 2 < total_gst) {
                    MBAR_EXPECT_TX(sb + OFF_MB + s * 8, 16384u);
                    bulk_g2s(sb + OFF_W(s), g_Wsw + (size_t)((gst + 2) & 31) * 16384,
                             16384u, sb + OFF_MB + s * 8);
                }
            }
        }

        // ---- epilogue: reduce across 4 lanes/row, then across 4 n-warps ----
        #pragma unroll
        for (int mi = 0; mi < 4; mi++)
            #pragma unroll
            for (int rh = 0; rh < 2; rh++) {
                rowacc[mi][rh] += __shfl_xor_sync(0xFFFFFFFFu, rowacc[mi][rh], 1);
                rowacc[mi][rh] += __shfl_xor_sync(0xFFFFFFFFu, rowacc[mi][rh], 2);
            }

        if ((lane & 3) == 0) {
            int g = lane >> 2;
            #pragma unroll
            for (int mi = 0; mi < 4; mi++)
                #pragma unroll
                for (int rh = 0; rh < 2; rh++) {
                    int m = mi * 16 + rh * 8 + g;
                    part[m * 4 + wid] = rowacc[mi][rh];
                }
        }
        __syncthreads();

        if (tid < 64) {
            float res = part[tid * 4 + 0] + part[tid * 4 + 1] +
                        part[tid * 4 + 2] + part[tid * 4 + 3] + b3v;
            int i = i0 + (tid >> 3);
            int j = j0 + (tid & 7);
            out[i * BB + j] = res;
        }
    }
}

// ============================================================================
// Host launcher
// ============================================================================
extern "C" void kernel_launch(void* const* d_in, const int* in_sizes, int n_in,
                              void* d_out, int out_size) {
    const float* x  = (const float*)d_in[0];
    const float* y  = (const float*)d_in[1];
    const float* W1 = (const float*)d_in[2];
    const float* b1 = (const float*)d_in[3];
    const float* W2 = (const float*)d_in[4];
    const float* b2 = (const float*)d_in[5];
    const float* W3 = (const float*)d_in[6];
    const float* b3 = (const float*)d_in[7];
    float* out = (float*)d_out;

    cudaFuncSetAttribute(k_main, cudaFuncAttributeMaxDynamicSharedMemorySize, SMEM_BYTES);

    k_prep<<<1024, 256>>>(x, y, W1, b1, W2);
    k_main<<<NCTA, 128, SMEM_BYTES>>>(b2, W3, b3, out);
}

// round 13
// speedup vs baseline: 1.2664x; 1.0547x over previous
#include <cuda_runtime.h>
#include <cuda_fp16.h>
#include <cstdint>

// ============================================================================
// out[i,j] = w3 . relu(W2 . relu(hx_i + hy_j + b1) + b2) + b3
// B = 512, H = 512, DX = DY = 128
// ============================================================================
#define BB 512
#define HH 512
#define NCTA 148          // persistent, 1 CTA/SM
#define NTILE 2048        // 128-pair tiles (8i x 16j)

__device__ __align__(128)  float  g_hx[BB * HH];           // x@W1[:, :128]^T + b1
__device__ __align__(128)  float  g_hy[BB * HH];           // y@W1[:, 128:]^T
// W2 fp16, pre-swizzled: 16 slabs (sid = nc*4 + kq) of 32KB (n128 x k128).
// slab: row n_local (0..127) * 256B; 16B chunk c (=k_local>>3, 0..15) at
// ((c ^ (n_local&7)) << 4); fp16 pair at (k_local&7)*2.
__device__ __align__(1024) unsigned char g_Wsw[HH * HH * 2];

// k_main SMEM layout (dynamic, bytes)
#define OFF_A    0                         // 128 rows x 1024B (fp16, swizzled)
#define OFF_W(s) (131072 + (s) * 32768)    // 2 x 32KB W slabs
#define OFF_B2   196608                    // 512 f32
#define OFF_W3   198656                    // 512 f32
#define OFF_MB   200704                    // 2 mbarriers (16B) + 2 counters (8B)
#define OFF_PART 200736                    // 128 x 4 f32 epilogue scratch
#define SMEM_BYTES 202784

static __device__ __forceinline__ uint32_t smem_u32(const void* p) {
    uint32_t a;
    asm("{ .reg .u64 t; cvta.to.shared.u64 t, %1; cvt.u32.u64 %0, t; }" : "=r"(a) : "l"(p));
    return a;
}
#define MBAR_INIT(addr, cnt) \
    asm volatile("mbarrier.init.shared.b64 [%0], %1;" :: "r"(addr), "r"(cnt) : "memory")
#define MBAR_EXPECT_TX(addr, bytes) \
    asm volatile("mbarrier.arrive.expect_tx.shared.b64 _, [%0], %1;" :: "r"(addr), "r"(bytes) : "memory")
#define MBAR_WAIT(addr, ph) do {                                                \
    uint32_t _m = (addr), _p = (ph), _d;                                        \
    asm volatile("{\n\t.reg .pred p;\n\t"                                       \
        "mbarrier.try_wait.parity.acquire.cta.shared::cta.b64 p, [%1], %2;\n\t" \
        "selp.b32 %0, 1, 0, p;\n\t}" : "=r"(_d) : "r"(_m), "r"(_p) : "memory"); \
    if (!_d) {                                                                  \
        asm volatile("{\n\t.reg .pred P;\n\tWL%=:\n\t"                          \
            "mbarrier.try_wait.parity.acquire.cta.shared::cta.b64 P, [%0], %1, 0x989680;\n\t" \
            "@P bra.uni WD%=;\n\tbra.uni WL%=;\n\tWD%=:\n\t}"                   \
            :: "r"(_m), "r"(_p) : "memory");                                    \
    }                                                                           \
} while (0)
static __device__ __forceinline__ void bulk_g2s(uint32_t dst, const void* src,
                                                uint32_t bytes, uint32_t mbar) {
    asm volatile(
        "cp.async.bulk.shared::cluster.global.mbarrier::complete_tx::bytes [%0], [%1], %2, [%3];"
        :: "r"(dst), "l"(src), "r"(bytes), "r"(mbar) : "memory");
}
static __device__ __forceinline__ void ldsm_x4(uint32_t& r0, uint32_t& r1, uint32_t& r2,
                                               uint32_t& r3, uint32_t addr) {
    asm volatile("ldmatrix.sync.aligned.m8n8.x4.shared.b16 {%0,%1,%2,%3}, [%4];"
                 : "=r"(r0), "=r"(r1), "=r"(r2), "=r"(r3) : "r"(addr));
}
static __device__ __forceinline__ void mma16816(float* d, const uint32_t* a, const uint32_t* b) {
    asm volatile(
        "mma.sync.aligned.m16n8k16.row.col.f32.f16.f16.f32 "
        "{%0,%1,%2,%3}, {%4,%5,%6,%7}, {%8,%9}, {%0,%1,%2,%3};"
        : "+f"(d[0]), "+f"(d[1]), "+f"(d[2]), "+f"(d[3])
        : "r"(a[0]), "r"(a[1]), "r"(a[2]), "r"(a[3]), "r"(b[0]), "r"(b[1]));
}

// ============================================================================
// Kernel 1: prep = first linear (blocks 0..511) + W2 quant/swizzle (512..1023)
// ============================================================================
__global__ void __launch_bounds__(256) k_prep(const float* __restrict__ x,
                                              const float* __restrict__ y,
                                              const float* __restrict__ W1,
                                              const float* __restrict__ b1,
                                              const float* __restrict__ W2) {
    int b = blockIdx.x;
    if (b >= 512) {
        // quant: 2 consecutive h per thread; layout = 16 slabs of 32KB
        int idx = ((b - 512) * 256 + threadIdx.x) * 2;
        int n = idx >> 9, h = idx & 511;
        int n_local = n & 127;
        int sid = (n >> 7) * 4 + (h >> 7);
        int k_local = h & 127;
        uint32_t c = (uint32_t)(k_local >> 3);
        uint32_t off = (uint32_t)n_local * 256 +
                       ((c ^ (uint32_t)(n_local & 7)) << 4) + (uint32_t)(k_local & 7) * 2;
        float2 v = *(const float2*)(W2 + (size_t)n * HH + h);
        __half2 hv;
        hv.x = __float2half_rn(v.x);
        hv.y = __float2half_rn(v.y);
        *(uint32_t*)(g_Wsw + (size_t)sid * 32768 + off) = *(uint32_t*)&hv;
        return;
    }
    __shared__ float xs_t[128][33];
    __shared__ float ws[32][128];
    int path = b >> 8;
    int rem = b & 255;
    int i0 = (rem & 15) * 32, h0 = (rem >> 4) * 32;
    const float* src = path ? y : x;
    int colOff = path ? 128 : 0;

    for (int v = threadIdx.x; v < 32 * 128; v += 256) {
        int i = v >> 7, d = v & 127;
        xs_t[d][i] = src[(i0 + i) * 128 + d];
    }
    for (int v = threadIdx.x; v < 32 * 32; v += 256) {
        int r = v >> 5, c4 = v & 31;
        ((float4*)&ws[r][0])[c4] = ((const float4*)&W1[(h0 + r) * 256 + colOff])[c4];
    }
    __syncthreads();

    int ti = threadIdx.x & 31, th = threadIdx.x >> 5;
    float acc0 = 0.f, acc1 = 0.f, acc2 = 0.f, acc3 = 0.f;
    #pragma unroll 4
    for (int d = 0; d < 128; d++) {
        float xv = xs_t[d][ti];
        acc0 = fmaf(xv, ws[th * 4 + 0][d], acc0);
        acc1 = fmaf(xv, ws[th * 4 + 1][d], acc1);
        acc2 = fmaf(xv, ws[th * 4 + 2][d], acc2);
        acc3 = fmaf(xv, ws[th * 4 + 3][d], acc3);
    }
    float* dst = path ? g_hy : g_hx;
    int i = i0 + ti;
    int hb = h0 + th * 4;
    float a0 = path ? 0.f : b1[hb + 0];
    float a1 = path ? 0.f : b1[hb + 1];
    float a2 = path ? 0.f : b1[hb + 2];
    float a3 = path ? 0.f : b1[hb + 3];
    dst[i * HH + hb + 0] = acc0 + a0;
    dst[i * HH + hb + 1] = acc1 + a1;
    dst[i * HH + hb + 2] = acc2 + a2;
    dst[i * HH + hb + 3] = acc3 + a3;
}

// ============================================================================
// Kernel 2: persistent main pair-GEMM + fused epilogue.
//   grid 148 (1 CTA/SM), block 256 (8 warps).  Each CTA loops tiles
//   t = bid, bid+148, ...  Tile: 128 pairs (8i x 16j), 16 steps of 32KB W
//   (n128 x k128).  W double-buffer pipeline runs CONTINUOUSLY across tiles
//   (global step gst); warp grid 2m x 4n, warp tile m64 x n32.
// ============================================================================
__global__ void __launch_bounds__(256, 1) k_main(const float* __restrict__ b2g,
                                                 const float* __restrict__ w3g,
                                                 const float* __restrict__ b3g,
                                                 float* __restrict__ out) {
    extern __shared__ __align__(1024) unsigned char smem[];
    uint32_t sb = smem_u32(smem);
    int tid = threadIdx.x, wid = tid >> 5, lane = tid & 31;

    float* b2s = (float*)(smem + OFF_B2);
    float* w3s = (float*)(smem + OFF_W3);
    float* part = (float*)(smem + OFF_PART);

    // tiles handled by this CTA
    int ntiles = 0;
    for (int t = blockIdx.x; t < NTILE; t += NCTA) ntiles++;
    int total_gst = ntiles * 16;

    // ---- one-time init: mbarriers/counters + first two W slabs + b2/w3 ----
    if (tid == 0) {
        MBAR_INIT(sb + OFF_MB + 0, 1);
        MBAR_INIT(sb + OFF_MB + 8, 1);
        *(int*)(smem + OFF_MB + 16) = 0;
        *(int*)(smem + OFF_MB + 20) = 0;
        asm volatile("fence.proxy.async.shared::cta;" ::: "memory");
        MBAR_EXPECT_TX(sb + OFF_MB + 0, 32768u);
        bulk_g2s(sb + OFF_W(0), g_Wsw + 0 * 32768, 32768u, sb + OFF_MB + 0);
        MBAR_EXPECT_TX(sb + OFF_MB + 8, 32768u);
        bulk_g2s(sb + OFF_W(1), g_Wsw + 1 * 32768, 32768u, sb + OFF_MB + 8);
    }
    for (int v = tid; v < 512; v += 256) {
        b2s[v] = b2g[v];
        w3s[v] = w3g[v];
    }
    float b3v = b3g[0];

    // ---- lane geometry (tile-independent): warp grid 2m x 4n, m64 x n32 ----
    int wm = wid >> 2;          // 0..1 -> m0 = wm*64
    int wn = wid & 3;           // 0..3 -> n0 = wn*32 within n-chunk 128
    int m0 = wm * 64, n0 = wn * 32;

    uint32_t x7 = (uint32_t)(lane & 7);
    uint32_t aHi = (uint32_t)(lane >> 4);
    uint32_t aRow[4];
    #pragma unroll
    for (int mi = 0; mi < 4; mi++)
        aRow[mi] = sb + OFF_A + (uint32_t)(m0 + mi * 16 + (lane & 15)) * 1024;
    uint32_t bRowOff = (uint32_t)(n0 + (lane & 7) + ((lane >> 4) << 3)) * 256;
    uint32_t bHi = (uint32_t)((lane >> 3) & 1);

    int gst = 0;

    #pragma unroll 1
    for (int t = blockIdx.x; t < NTILE; t += NCTA) {
        int i0 = (t >> 5) * 8, j0 = (t & 31) * 16;

        // ---- tile boundary: all warps done with previous A / part ----
        __syncthreads();

        // ---- build A = relu(hx_i + hy_j) fp16 (register-blocked, 1 col/th) ----
        {
            int kk = tid;  // half2 column 0..255
            float2 hyv[16];
            #pragma unroll
            for (int j = 0; j < 16; j++)
                hyv[j] = ((const float2*)(g_hy + (j0 + j) * HH))[kk];
            uint32_t base = sb + OFF_A + (uint32_t)(kk & 3) * 4;
            uint32_t chunk = (uint32_t)(kk >> 2);
            #pragma unroll
            for (int ig = 0; ig < 8; ig++) {
                float2 hx2 = ((const float2*)(g_hx + (i0 + ig) * HH))[kk];
                #pragma unroll
                for (int j = 0; j < 16; j++) {
                    float v0 = fmaxf(hx2.x + hyv[j].x, 0.f);
                    float v1 = fmaxf(hx2.y + hyv[j].y, 0.f);
                    __half2 hv;
                    hv.x = __float2half_rn(v0);
                    hv.y = __float2half_rn(v1);
                    uint32_t p = (uint32_t)(ig * 16 + j);
                    uint32_t addr = base + p * 1024 + ((chunk ^ (p & 7)) << 4);
                    asm volatile("st.shared.b32 [%0], %1;"
                                 :: "r"(addr), "r"(*(uint32_t*)&hv) : "memory");
                }
            }
        }
        __syncthreads();   // A visible (covers one-time init on first tile)

        float d[4][4][4];                 // [mi][ni][q]
        float rowacc[4][2];               // [mi][row half]
        #pragma unroll
        for (int mi = 0; mi < 4; mi++) { rowacc[mi][0] = 0.f; rowacc[mi][1] = 0.f; }

        #pragma unroll 1
        for (int st = 0; st < 16; st++, gst++) {
            int s = gst & 1, kq = st & 3;
            MBAR_WAIT(sb + OFF_MB + s * 8, (gst >> 1) & 1);

            if (kq == 0) {
                #pragma unroll
                for (int mi = 0; mi < 4; mi++)
                    #pragma unroll
                    for (int ni = 0; ni < 4; ni++)
                        #pragma unroll
                        for (int q = 0; q < 4; q++) d[mi][ni][q] = 0.f;
            }

            uint32_t bBase = sb + OFF_W(s) + bRowOff;
            uint32_t aChunk0 = (uint32_t)(kq * 16);

            #pragma unroll
            for (int kk = 0; kk < 8; kk++) {
                uint32_t aswz = (((aChunk0 + (uint32_t)(kk << 1) + aHi) ^ x7) << 4);
                uint32_t bswz = ((((uint32_t)(kk << 1) + bHi) ^ x7) << 4);
                uint32_t a[4][4], b0[4], b1[4];
                #pragma unroll
                for (int mi = 0; mi < 4; mi++)
                    ldsm_x4(a[mi][0], a[mi][1], a[mi][2], a[mi][3], aRow[mi] + aswz);
                ldsm_x4(b0[0], b0[1], b0[2], b0[3], bBase + bswz);
                ldsm_x4(b1[0], b1[1], b1[2], b1[3], bBase + 16 * 256 + bswz);
                #pragma unroll
                for (int mi = 0; mi < 4; mi++) {
                    mma16816(d[mi][0], a[mi], b0 + 0);
                    mma16816(d[mi][1], a[mi], b0 + 2);
                    mma16816(d[mi][2], a[mi], b1 + 0);
                    mma16816(d[mi][3], a[mi], b1 + 2);
                }
            }

            if (kq == 3) {
                // fold: rowacc += sum_n relu(D + b2[n]) * w3[n]
                int ncol = (st >> 2) * 128 + n0 + (lane & 3) * 2;
                #pragma unroll
                for (int ni = 0; ni < 4; ni++) {
                    int c0 = ncol + ni * 8, c1 = c0 + 1;
                    float bb0 = b2s[c0], bb1 = b2s[c1];
                    float ww0 = w3s[c0], ww1 = w3s[c1];
                    #pragma unroll
                    for (int mi = 0; mi < 4; mi++) {
                        rowacc[mi][0] = fmaf(fmaxf(d[mi][ni][0] + bb0, 0.f), ww0, rowacc[mi][0]);
                        rowacc[mi][0] = fmaf(fmaxf(d[mi][ni][1] + bb1, 0.f), ww1, rowacc[mi][0]);
                        rowacc[mi][1] = fmaf(fmaxf(d[mi][ni][2] + bb0, 0.f), ww0, rowacc[mi][1]);
                        rowacc[mi][1] = fmaf(fmaxf(d[mi][ni][3] + bb1, 0.f), ww1, rowacc[mi][1]);
                    }
                }
            }

            // last warp to finish this step issues the refetch into this slab
            if (lane == 0) {
                int old;
                asm volatile("atom.shared.add.s32 %0, [%1], 1;"
                             : "=r"(old) : "r"(sb + OFF_MB + 16 + s * 4) : "memory");
                if ((old & 7) == 7 && gst + 2 < total_gst) {
                    MBAR_EXPECT_TX(sb + OFF_MB + s * 8, 32768u);
                    bulk_g2s(sb + OFF_W(s), g_Wsw + (size_t)((gst + 2) & 15) * 32768,
                             32768u, sb + OFF_MB + s * 8);
                }
            }
        }

        // ---- epilogue: reduce across 4 lanes/row, then across 4 n-warps ----
        #pragma unroll
        for (int mi = 0; mi < 4; mi++)
            #pragma unroll
            for (int rh = 0; rh < 2; rh++) {
                rowacc[mi][rh] += __shfl_xor_sync(0xFFFFFFFFu, rowacc[mi][rh], 1);
                rowacc[mi][rh] += __shfl_xor_sync(0xFFFFFFFFu, rowacc[mi][rh], 2);
            }

        if ((lane & 3) == 0) {
            int g = lane >> 2;
            #pragma unroll
            for (int mi = 0; mi < 4; mi++)
                #pragma unroll
                for (int rh = 0; rh < 2; rh++) {
                    int m = m0 + mi * 16 + rh * 8 + g;
                    part[m * 4 + wn] = rowacc[mi][rh];
                }
        }
        __syncthreads();

        if (tid < 128) {
            float res = part[tid * 4 + 0] + part[tid * 4 + 1] +
                        part[tid * 4 + 2] + part[tid * 4 + 3] + b3v;
            int i = i0 + (tid >> 4);
            int j = j0 + (tid & 15);
            out[i * BB + j] = res;
        }
    }
}

// ============================================================================
// Host launcher
// ============================================================================
extern "C" void kernel_launch(void* const* d_in, const int* in_sizes, int n_in,
                              void* d_out, int out_size) {
    const float* x  = (const float*)d_in[0];
    const float* y  = (const float*)d_in[1];
    const float* W1 = (const float*)d_in[2];
    const float* b1 = (const float*)d_in[3];
    const float* W2 = (const float*)d_in[4];
    const float* b2 = (const float*)d_in[5];
    const float* W3 = (const float*)d_in[6];
    const float* b3 = (const float*)d_in[7];
    float* out = (float*)d_out;

    cudaFuncSetAttribute(k_main, cudaFuncAttributeMaxDynamicSharedMemorySize, SMEM_BYTES);

    k_prep<<<1024, 256>>>(x, y, W1, b1, W2);
    k_main<<<NCTA, 256, SMEM_BYTES>>>(b2, W3, b3, out);
}